// round 16
// baseline (speedup 1.0000x reference)
#include <cuda_runtime.h>
#include <cstdint>

#define NB 48
#define NL 17
#define ND 256
#define NM 768    /* NB*(L-1) */
#define PAIR_BLOCKS 768
#define NTILES 90 /* 78 upper-tri tok tiles + 12 anchor-row tiles */
#define NCAND (NB*NM)          /* 36864 pair candidates */
#define CPB 410                /* candidates per gemm block: 90*410 >= 36864 */

#define SCALE_C  4294967296.0f           /* 2^32 for csum fixed-point */
#define SCALE_KL 1.125899906842624e15f   /* 2^50 for kl fixed-point */

__device__ float g_E   [832*NM];  // exp(sims): rows 0..767 Et, 768..815 Ea
__device__ int   g_pairs[NCAND];  // (b<<16)|j, unordered (consumers order-free)
__device__ unsigned int       g_pcnt;        // zero-init; reset by k_pairs final block
__device__ unsigned long long g_csum  [NB];  // sum_neg Ea[b,k] * 2^32
__device__ unsigned long long g_rowsum[NB];  // sum_j kl[b,j]   * 2^50
__device__ unsigned int       g_done;

// ---------------------------------------------------------------- utilities
__device__ __forceinline__ float tf32r(float x) {
    float h;
    asm("cvt.rna.tf32.f32 %0, %1;" : "=f"(h) : "f"(x));
    return h;
}
__device__ __forceinline__ void mma_tf32(float& d0, float& d1, float& d2, float& d3,
                                         uint32_t a0, uint32_t a1, uint32_t a2,
                                         uint32_t a3, uint32_t b0, uint32_t b1) {
    asm volatile(
        "mma.sync.aligned.m16n8k8.row.col.f32.tf32.tf32.f32 "
        "{%0,%1,%2,%3}, {%4,%5,%6,%7}, {%8,%9}, {%0,%1,%2,%3};"
        : "+f"(d0), "+f"(d1), "+f"(d2), "+f"(d3)
        : "r"(a0), "r"(a1), "r"(a2), "r"(a3), "r"(b0), "r"(b1));
}

// logical row g (0..831: toks, anchors, pad) -> input row of x, or -1 for pad
__device__ __forceinline__ int xrow_of(int g) {
    if (g >= 816) return -1;
    if (g >= NM)  return (g - NM) * NL;          // anchor b -> x row b*17
    return (g >> 4) * NL + 1 + (g & 15);         // tok -> b*17 + 1 + p
}

// Reference declares int64 labels; jax w/o x64 silently yields int32. An
// int64 buffer (values 0..7, little-endian) read as int32 is [v,0,v,0,...].
__device__ __forceinline__ void load_labels(const int* __restrict__ lab32,
                                            int* lab, int* flag) {
    int t = threadIdx.x;
    if (t == 0) {
        bool is64 = true;
        for (int i = 1; i < NB; i += 2) if (lab32[i] != 0) { is64 = false; break; }
        if (is64) for (int i = 0; i < NB; i += 2) {
            int v = lab32[i];
            if (v < 0 || v >= 8) { is64 = false; break; }
        }
        *flag = is64 ? 1 : 0;
    }
    __syncthreads();
    if (t < NB) lab[t] = (*flag) ? (int)((const long long*)lab32)[t] : lab32[t];
    __syncthreads();
}

// ---- 1: everything-fused GEMM. Per block: pair-build slice, inline row
// normalization from x, tf32x3 mma tile, exp epilogue, mirror write for
// off-diag tok tiles, fixed-point csum on anchor-row tiles (jt==12).
// tiles: id 0..77 -> (jt,kt) upper triangle of 12x12 tok grid; 78..89 -> (12,kt)
// smem tiles stride 36 floats: fragment banks = (4n + k) mod 32, conflict-free.
__global__ void __launch_bounds__(256) k_gemm(const float* __restrict__ x,
                                              const int* __restrict__ lab32) {
    __shared__ __align__(16) float sbuf[4 * 64 * 36];   // Ah, Al, Bh, Bl (36.9KB)
    __shared__ int   lab[NB];
    __shared__ int   flag;
    __shared__ float inv_s[128];
    __shared__ int   xrow_s[128];
    __shared__ int   wc[8];
    __shared__ unsigned base_s;
    float* sAh = sbuf;
    float* sAl = sbuf + 2304;
    float* sBh = sbuf + 4608;
    float* sBl = sbuf + 6912;
    int t = threadIdx.x, w = t >> 5, lane = t & 31;
    int wr = (w & 3) * 16, wn = (w >> 2) * 32;          // warp tile: rows 16, cols 32

    load_labels(lab32, lab, &flag);

    int id = blockIdx.x, jt, kt;
    if (id < 78) {
        jt = 0; int rem = id;
        while (rem >= 12 - jt) { rem -= 12 - jt; jt++; }
        kt = jt + rem;
    } else { jt = 12; kt = id - 78; }
    int jb = jt * 64, kb = kt * 64;

    // ---- pair-build slice (one aggregated atomic per 256-candidate round)
    {
        int base_c = id * CPB;
        #pragma unroll
        for (int q = 0; q < 2; q++) {
            int rel = q * 256 + t;
            int ci = base_c + rel;
            bool a = false; int pv = 0;
            if (rel < CPB && ci < NCAND) {
                int b = ci / NM, j = ci - b * NM;
                a = (lab[j >> 4] == lab[b]);
                pv = (b << 16) | j;
            }
            unsigned bal = __ballot_sync(0xffffffffu, a);
            if (lane == 0) wc[w] = __popc(bal);
            __syncthreads();
            if (t == 0) {
                int tot = 0;
                #pragma unroll
                for (int i = 0; i < 8; i++) tot += wc[i];
                base_s = atomicAdd(&g_pcnt, (unsigned)tot);
            }
            __syncthreads();
            int off = 0;
            #pragma unroll
            for (int i = 0; i < 8; i++) if (i < w) off += wc[i];
            if (a)
                g_pairs[base_s + off + __popc(bal & ((1u << lane) - 1u))] = pv;
            __syncthreads();
        }
    }

    // ---- inline inv-norms for both panels (warp-per-row, same reduce as ever)
    for (int r = w; r < 128; r += 8) {
        int g  = (r < 64) ? (jb + r) : (kb + (r - 64));
        int xr = xrow_of(g);
        float ss = 0.f;
        if (xr >= 0) {
            const float4* src = (const float4*)&x[xr * ND];
            float4 v0 = src[lane], v1 = src[lane + 32];
            ss = v0.x*v0.x + v0.y*v0.y + v0.z*v0.z + v0.w*v0.w
               + v1.x*v1.x + v1.y*v1.y + v1.z*v1.z + v1.w*v1.w;
        }
        #pragma unroll
        for (int o = 16; o > 0; o >>= 1) ss += __shfl_xor_sync(0xffffffffu, ss, o);
        if (lane == 0) {
            inv_s[r]  = (xr >= 0) ? 1.f / fmaxf(sqrtf(ss), 1e-12f) : 0.f;
            xrow_s[r] = xr;
        }
    }
    __syncthreads();

    // prefetch chunk 0 (Kc = 32): one x float4 per panel per slot
    float4 pf[4];
    #pragma unroll
    for (int u = 0; u < 2; u++) {
        int idx = t + u * 256, row = idx >> 3, c4 = (idx & 7) * 4;
        int xj = xrow_s[row], xk = xrow_s[64 + row];
        pf[u*2+0] = (xj >= 0) ? *(const float4*)&x[xj * ND + c4]
                              : make_float4(0.f, 0.f, 0.f, 0.f);
        pf[u*2+1] = (xk >= 0) ? *(const float4*)&x[xk * ND + c4]
                              : make_float4(0.f, 0.f, 0.f, 0.f);
    }

    float acc[4][4] = {};                // 4 n-blocks x 4 regs (m16n8 frags)
    int ar0 = (wr + (lane >> 2)) * 36 + (lane & 3);
    for (int ch = 0; ch < 8; ch++) {
        __syncthreads();
        #pragma unroll
        for (int u = 0; u < 2; u++) {
            int idx = t + u * 256, row = idx >> 3, c4 = (idx & 7) * 4;
            float ivj = inv_s[row], ivk = inv_s[64 + row];
            float4 vj = pf[u*2+0], vk = pf[u*2+1];
            float nj0 = vj.x*ivj, nj1 = vj.y*ivj, nj2 = vj.z*ivj, nj3 = vj.w*ivj;
            float hj0 = tf32r(nj0), hj1 = tf32r(nj1), hj2 = tf32r(nj2), hj3 = tf32r(nj3);
            *(float4*)&sAh[row * 36 + c4] = make_float4(hj0, hj1, hj2, hj3);
            *(float4*)&sAl[row * 36 + c4] = make_float4(tf32r(nj0-hj0), tf32r(nj1-hj1),
                                                        tf32r(nj2-hj2), tf32r(nj3-hj3));
            float nk0 = vk.x*ivk, nk1 = vk.y*ivk, nk2 = vk.z*ivk, nk3 = vk.w*ivk;
            float hk0 = tf32r(nk0), hk1 = tf32r(nk1), hk2 = tf32r(nk2), hk3 = tf32r(nk3);
            *(float4*)&sBh[row * 36 + c4] = make_float4(hk0, hk1, hk2, hk3);
            *(float4*)&sBl[row * 36 + c4] = make_float4(tf32r(nk0-hk0), tf32r(nk1-hk1),
                                                        tf32r(nk2-hk2), tf32r(nk3-hk3));
        }
        __syncthreads();
        if (ch < 7) {
            int k0g = (ch + 1) * 32;
            #pragma unroll
            for (int u = 0; u < 2; u++) {
                int idx = t + u * 256, row = idx >> 3, c4 = (idx & 7) * 4;
                int xj = xrow_s[row], xk = xrow_s[64 + row];
                pf[u*2+0] = (xj >= 0) ? *(const float4*)&x[xj * ND + k0g + c4]
                                      : make_float4(0.f, 0.f, 0.f, 0.f);
                pf[u*2+1] = (xk >= 0) ? *(const float4*)&x[xk * ND + k0g + c4]
                                      : make_float4(0.f, 0.f, 0.f, 0.f);
            }
        }
        #pragma unroll
        for (int ks = 0; ks < 4; ks++) {
            int k0 = ks * 8;
            uint32_t ah0 = __float_as_uint(sAh[ar0 + k0]);
            uint32_t ah1 = __float_as_uint(sAh[ar0 + 8 * 36 + k0]);
            uint32_t ah2 = __float_as_uint(sAh[ar0 + k0 + 4]);
            uint32_t ah3 = __float_as_uint(sAh[ar0 + 8 * 36 + k0 + 4]);
            uint32_t al0 = __float_as_uint(sAl[ar0 + k0]);
            uint32_t al1 = __float_as_uint(sAl[ar0 + 8 * 36 + k0]);
            uint32_t al2 = __float_as_uint(sAl[ar0 + k0 + 4]);
            uint32_t al3 = __float_as_uint(sAl[ar0 + 8 * 36 + k0 + 4]);
            #pragma unroll
            for (int nb = 0; nb < 4; nb++) {
                int br = (wn + nb * 8 + (lane >> 2)) * 36 + k0 + (lane & 3);
                uint32_t bh0 = __float_as_uint(sBh[br]);
                uint32_t bh1 = __float_as_uint(sBh[br + 4]);
                uint32_t bl0 = __float_as_uint(sBl[br]);
                uint32_t bl1 = __float_as_uint(sBl[br + 4]);
                mma_tf32(acc[nb][0], acc[nb][1], acc[nb][2], acc[nb][3],
                         ah0, ah1, ah2, ah3, bh0, bh1);
                mma_tf32(acc[nb][0], acc[nb][1], acc[nb][2], acc[nb][3],
                         ah0, ah1, ah2, ah3, bl0, bl1);
                mma_tf32(acc[nb][0], acc[nb][1], acc[nb][2], acc[nb][3],
                         al0, al1, al2, al3, bh0, bh1);
            }
        }
    }

    // stage exp(result) in Tr[64][65] (aliases sbuf: 4160 <= 9216 floats)
    __syncthreads();
    float* Tr = sbuf;
    {
        int r0 = wr + (lane >> 2), c0 = wn + 2 * (lane & 3);
        #pragma unroll
        for (int nb = 0; nb < 4; nb++) {
            int cc = c0 + nb * 8;
            Tr[r0 * 65 + cc]           = __expf(acc[nb][0]);
            Tr[r0 * 65 + cc + 1]       = __expf(acc[nb][1]);
            Tr[(r0 + 8) * 65 + cc]     = __expf(acc[nb][2]);
            Tr[(r0 + 8) * 65 + cc + 1] = __expf(acc[nb][3]);
        }
    }
    __syncthreads();

    // coalesced E write
    #pragma unroll
    for (int u = 0; u < 4; u++) {
        int idx = t + u * 256;           // 1024 float4 = 64 rows x 16
        int r = idx >> 4, c4 = (idx & 15) * 4;
        float4 v = make_float4(Tr[r*65 + c4], Tr[r*65 + c4 + 1],
                               Tr[r*65 + c4 + 2], Tr[r*65 + c4 + 3]);
        *(float4*)&g_E[(jb + r) * NM + kb + c4] = v;
    }
    if (jt < 12) {
        if (jt != kt) {                  // transpose mirror
            #pragma unroll
            for (int u = 0; u < 4; u++) {
                int idx = t + u * 256;
                int r = idx >> 4, c4 = (idx & 15) * 4;
                float4 v = make_float4(Tr[(c4+0)*65 + r], Tr[(c4+1)*65 + r],
                                       Tr[(c4+2)*65 + r], Tr[(c4+3)*65 + r]);
                *(float4*)&g_E[(kb + r) * NM + jb + c4] = v;
            }
        }
    } else if (t < NB) {                 // anchor-row tile: csum (fixed-point)
        int mb = lab[t];
        float part = 0.f;
        #pragma unroll 8
        for (int cc = 0; cc < 64; cc++)
            if (lab[(kb + cc) >> 4] != mb) part += Tr[t * 65 + cc];
        atomicAdd(&g_csum[t], (unsigned long long)(long long)llrintf(part * SCALE_C));
    }
}

// ---- 2: warp-per-pair symmetric KL (cancellation-free) + in-kernel finish
// e=c*Et, a=c*Ea, t=e-a, mu=exp(e)-1 (series), d=mu-nu=t*h (series)
// symKL = 0.5*(Sdt*D1 - Sd*N1)/(D1*D2); D1=n+Smu, N1=St+Smut, D2=D1-Sd
// Pair order is irrelevant: per-pair kl is a pure function of globals and the
// accumulation is integer fixed-point -> bit-identical across replays.
__global__ void k_pairs(const int* __restrict__ lab32, float* __restrict__ out) {
    __shared__ int lab[NB];
    __shared__ int flag;
    __shared__ float nneg_s[NB], P_s[NB];
    __shared__ unsigned int ticket_s;
    int t = threadIdx.x, lane = t & 31, w = t >> 5;
    load_labels(lab32, lab, &flag);
    if (t < NB) {
        int same = 0;
        #pragma unroll 8
        for (int o = 0; o < NB; o++) same += (lab[o] == lab[t]) ? 1 : 0;
        nneg_s[t] = (float)((NB - same) * (NL - 1));
        P_s[t]    = (float)(same * (NL - 1));
    }
    __syncthreads();
    int np = (int)g_pcnt;
    for (int p = blockIdx.x * 8 + w; p < np; p += PAIR_BLOCKS * 8) {
        int pr = g_pairs[p];
        int b = pr >> 16, j = pr & 0xffff;
        int mb = lab[b];
        float c = SCALE_C / (float)(long long)g_csum[b];
        const float* Et = g_E + j * NM;
        const float* Ea = g_E + (NM + b) * NM;

        float s0 = 0.f, s1 = 0.f, s2 = 0.f, s3 = 0.f, s4 = 0.f;
        #pragma unroll
        for (int i = 0; i < 6; i++) {    // float4 per lane; 4 k share one mask
            int k4 = i * 128 + lane * 4;
            float m = (lab[k4 >> 4] != mb) ? c : 0.f;
            float4 E4 = *(const float4*)&Et[k4];
            float4 A4 = *(const float4*)&Ea[k4];
            #pragma unroll
            for (int u = 0; u < 4; u++) {
                float Ev = (u == 0) ? E4.x : (u == 1) ? E4.y : (u == 2) ? E4.z : E4.w;
                float Av = (u == 0) ? A4.x : (u == 1) ? A4.y : (u == 2) ? A4.z : A4.w;
                float e  = m * Ev;
                float a  = m * Av;
                float tt = e - a;
                float mu = e * (1.f + e * (0.5f + e * (1.f/6.f)));
                float sp = e + a;
                float e2 = e * e, ea = e * a, a2 = a * a;
                float h  = 1.f + 0.5f * sp + (e2 + ea + a2) * (1.f/6.f);
                float d  = tt * h;
                s0 += tt; s1 += mu; s2 = fmaf(mu, tt, s2);
                s3 += d;  s4 = fmaf(tt, d, s4);
            }
        }
        #pragma unroll
        for (int o = 16; o > 0; o >>= 1) {
            s0 += __shfl_down_sync(0xffffffffu, s0, o);
            s1 += __shfl_down_sync(0xffffffffu, s1, o);
            s2 += __shfl_down_sync(0xffffffffu, s2, o);
            s3 += __shfl_down_sync(0xffffffffu, s3, o);
            s4 += __shfl_down_sync(0xffffffffu, s4, o);
        }
        if (lane == 0) {
            float n  = nneg_s[b];
            float D1 = n + s1;
            float N1 = s0 + s2;
            float D2 = D1 - s3;
            float kl = 0.5f * (s4 * D1 - s3 * N1) / (D1 * D2);
            atomicAdd(&g_rowsum[b],
                      (unsigned long long)(long long)llrintf(kl * SCALE_KL));
        }
    }
    // last block: final scalar + reset all counters for the next graph replay
    __threadfence();
    __syncthreads();
    if (t == 0) ticket_s = atomicAdd(&g_done, 1u);
    __syncthreads();
    if (ticket_s == PAIR_BLOCKS - 1 && t == 0) {
        float tot = 0.f;
        for (int b = 0; b < NB; b++) {
            float rs = (float)(long long)g_rowsum[b] * (1.f / SCALE_KL);
            tot += rs / P_s[b];
            g_rowsum[b] = 0ull;
            g_csum[b]   = 0ull;
        }
        out[0] = tot / (float)NB;
        g_pcnt = 0u;
        g_done = 0u;
    }
}

// ----------------------------------------------------------------- launch
extern "C" void kernel_launch(void* const* d_in, const int* in_sizes, int n_in,
                              void* d_out, int out_size) {
    const float* x     = (const float*)d_in[0];
    const int*   lab32 = (const int*)  d_in[1];
    float*       out   = (float*)      d_out;
    (void)in_sizes; (void)n_in; (void)out_size;

    k_gemm <<<NTILES, 256>>>(x, lab32);
    k_pairs<<<PAIR_BLOCKS, 256>>>(lab32, out);
}

// round 17
// speedup vs baseline: 1.2947x; 1.2947x over previous
#include <cuda_runtime.h>
#include <cstdint>

#define NB 48
#define NL 17
#define ND 256
#define NM 768    /* NB*(L-1) */
#define NR 832    /* NM + NB anchors = 13*64 */
#define PAIR_BLOCKS 768
#define NTILES 90 /* 78 upper-tri tok tiles + 12 anchor-row tiles */
#define PREP_BLOCKS 249

#define SCALE_C  4294967296.0f           /* 2^32 for csum fixed-point */
#define SCALE_KL 1.125899906842624e15f   /* 2^50 for kl fixed-point */

__device__ float g_hi  [NR*ND];   // tf32-rounded normalized rows
__device__ float g_lo  [NR*ND];   // tf32 residual
__device__ float g_E   [NR*NM];   // exp(sims): rows 0..767 Et, 768..815 Ea
__device__ float g_nneg[NB];
__device__ float g_P   [NB];
__device__ int   g_lab [NB];
__device__ int   g_pairs[NB*NM];  // (b<<16)|j, unordered (consumers order-free)
__device__ unsigned int       g_pcnt;        // zero-init; reset by k_pairs final block
__device__ unsigned long long g_csum  [NB];  // sum_neg Ea[b,k] * 2^32
__device__ unsigned long long g_rowsum[NB];  // sum_j kl[b,j]   * 2^50
__device__ unsigned int       g_done;

// ---------------------------------------------------------------- utilities
__device__ __forceinline__ float tf32r(float x) {
    float h;
    asm("cvt.rna.tf32.f32 %0, %1;" : "=f"(h) : "f"(x));
    return h;
}
__device__ __forceinline__ void mma_tf32(float& d0, float& d1, float& d2, float& d3,
                                         uint32_t a0, uint32_t a1, uint32_t a2,
                                         uint32_t a3, uint32_t b0, uint32_t b1) {
    asm volatile(
        "mma.sync.aligned.m16n8k8.row.col.f32.tf32.tf32.f32 "
        "{%0,%1,%2,%3}, {%4,%5,%6,%7}, {%8,%9}, {%0,%1,%2,%3};"
        : "+f"(d0), "+f"(d1), "+f"(d2), "+f"(d3)
        : "r"(a0), "r"(a1), "r"(a2), "r"(a3), "r"(b0), "r"(b1));
}

// Reference declares int64 labels; jax w/o x64 silently yields int32. An
// int64 buffer (values 0..7, little-endian) read as int32 is [v,0,v,0,...].
__device__ __forceinline__ void load_labels(const int* __restrict__ lab32,
                                            int* lab, int* flag) {
    int t = threadIdx.x;
    if (t == 0) {
        bool is64 = true;
        for (int i = 1; i < NB; i += 2) if (lab32[i] != 0) { is64 = false; break; }
        if (is64) for (int i = 0; i < NB; i += 2) {
            int v = lab32[i];
            if (v < 0 || v >= 8) { is64 = false; break; }
        }
        *flag = is64 ? 1 : 0;
    }
    __syncthreads();
    if (t < NB) lab[t] = (*flag) ? (int)((const long long*)lab32)[t] : lab32[t];
    __syncthreads();
}

// ---- 0: prep. blocks 0..101: warp-per-row norm + tf32 hi/lo split (816 rows);
// 102..103: zero pads (rows 816..831); 104..247: pair list; 248: scalars.
__global__ void k_prep(const float* __restrict__ x, const int* __restrict__ lab32) {
    int bid = blockIdx.x, t = threadIdx.x, w = t >> 5, lane = t & 31;
    if (bid < 102) {
        int r = bid * 8 + w;             // 0..815
        const float4* src = (const float4*)&x[r * ND];
        float4 v0 = src[lane], v1 = src[lane + 32];
        float ss = v0.x*v0.x + v0.y*v0.y + v0.z*v0.z + v0.w*v0.w
                 + v1.x*v1.x + v1.y*v1.y + v1.z*v1.z + v1.w*v1.w;
        #pragma unroll
        for (int o = 16; o > 0; o >>= 1) ss += __shfl_xor_sync(0xffffffffu, ss, o);
        float inv = 1.f / fmaxf(sqrtf(ss), 1e-12f);
        int b = r / NL, p = r - b * NL;
        int row = (p == 0) ? (NM + b) : (b * (NL - 1) + p - 1);
        float4* dh = (float4*)&g_hi[row * ND];
        float4* dl = (float4*)&g_lo[row * ND];
        float4 n0 = make_float4(v0.x*inv, v0.y*inv, v0.z*inv, v0.w*inv);
        float4 n1 = make_float4(v1.x*inv, v1.y*inv, v1.z*inv, v1.w*inv);
        float4 h0 = make_float4(tf32r(n0.x), tf32r(n0.y), tf32r(n0.z), tf32r(n0.w));
        float4 h1 = make_float4(tf32r(n1.x), tf32r(n1.y), tf32r(n1.z), tf32r(n1.w));
        dh[lane]      = h0;
        dh[lane + 32] = h1;
        dl[lane]      = make_float4(tf32r(n0.x - h0.x), tf32r(n0.y - h0.y),
                                    tf32r(n0.z - h0.z), tf32r(n0.w - h0.w));
        dl[lane + 32] = make_float4(tf32r(n1.x - h1.x), tf32r(n1.y - h1.y),
                                    tf32r(n1.z - h1.z), tf32r(n1.w - h1.w));
        return;
    }
    if (bid < 104) {                     // zero pad rows 816..831
        int r = 816 + (bid - 102) * 8 + w;
        float4 z = make_float4(0.f, 0.f, 0.f, 0.f);
        float4* dh = (float4*)&g_hi[r * ND];
        float4* dl = (float4*)&g_lo[r * ND];
        dh[lane] = z; dh[lane + 32] = z;
        dl[lane] = z; dl[lane + 32] = z;
        return;
    }
    __shared__ int lab[NB];
    __shared__ int flag;
    load_labels(lab32, lab, &flag);
    if (bid < 248) {                     // pair list: ONE atomic per block
        __shared__ int wc[8];
        __shared__ unsigned base_s;
        int p = (bid - 104) * 256 + t;   // 0..36863
        int b = p / NM, j = p - b * NM;
        bool act = (lab[j >> 4] == lab[b]);
        unsigned bal = __ballot_sync(0xffffffffu, act);
        if (lane == 0) wc[w] = __popc(bal);
        __syncthreads();
        if (t == 0) {
            int tot = 0;
            #pragma unroll
            for (int i = 0; i < 8; i++) tot += wc[i];
            base_s = atomicAdd(&g_pcnt, (unsigned)tot);
        }
        __syncthreads();
        int off = 0;
        #pragma unroll
        for (int i = 0; i < 8; i++) if (i < w) off += wc[i];
        if (act)
            g_pairs[base_s + off + __popc(bal & ((1u << lane) - 1u))] = (b << 16) | j;
        return;
    }
    if (t < NB) {
        int same = 0;
        #pragma unroll 8
        for (int o = 0; o < NB; o++) same += (lab[o] == lab[t]) ? 1 : 0;
        g_lab[t]  = lab[t];
        g_nneg[t] = (float)((NB - same) * (NL - 1));
        g_P[t]    = (float)(same * (NL - 1));
    }
}

// ---- 1: symmetric GEMM via mma.sync tf32x3, exp epilogue, mirror write for
// off-diag tok tiles, fused csum on anchor-row tiles (jt==12).
// tiles: id 0..77 -> (jt,kt) upper triangle of 12x12 tok grid; 78..89 -> (12,kt)
// smem tiles stride 36 floats: fragment banks = (4n + k) mod 32, conflict-free.
__global__ void __launch_bounds__(256) k_gemm(void) {
    __shared__ __align__(16) float sbuf[4 * 64 * 36];   // Ah, Al, Bh, Bl (36.9KB)
    __shared__ int lab[NB];
    float* sAh = sbuf;
    float* sAl = sbuf + 2304;
    float* sBh = sbuf + 4608;
    float* sBl = sbuf + 6912;
    int t = threadIdx.x, w = t >> 5, lane = t & 31;
    int wr = (w & 3) * 16, wn = (w >> 2) * 32;          // warp tile: rows 16, cols 32
    if (t < NB) lab[t] = g_lab[t];

    int id = blockIdx.x, jt, kt;
    if (id < 78) {
        jt = 0; int rem = id;
        while (rem >= 12 - jt) { rem -= 12 - jt; jt++; }
        kt = jt + rem;
    } else { jt = 12; kt = id - 78; }
    int jb = jt * 64, kb = kt * 64;

    // prefetch chunk 0 (Kc = 32): 2 float4 per thread per buffer
    float4 pf[8];
    #pragma unroll
    for (int u = 0; u < 2; u++) {
        int idx = t + u * 256, row = idx >> 3, c4 = (idx & 7) * 4;
        pf[u * 4 + 0] = *(const float4*)&g_hi[(jb + row) * ND + c4];
        pf[u * 4 + 1] = *(const float4*)&g_lo[(jb + row) * ND + c4];
        pf[u * 4 + 2] = *(const float4*)&g_hi[(kb + row) * ND + c4];
        pf[u * 4 + 3] = *(const float4*)&g_lo[(kb + row) * ND + c4];
    }

    float acc[4][4] = {};                // 4 n-blocks x 4 regs (m16n8 frags)
    int ar0 = (wr + (lane >> 2)) * 36 + (lane & 3);
    for (int ch = 0; ch < 8; ch++) {
        __syncthreads();
        #pragma unroll
        for (int u = 0; u < 2; u++) {
            int idx = t + u * 256, row = idx >> 3, c4 = (idx & 7) * 4;
            *(float4*)&sAh[row * 36 + c4] = pf[u * 4 + 0];
            *(float4*)&sAl[row * 36 + c4] = pf[u * 4 + 1];
            *(float4*)&sBh[row * 36 + c4] = pf[u * 4 + 2];
            *(float4*)&sBl[row * 36 + c4] = pf[u * 4 + 3];
        }
        __syncthreads();
        if (ch < 7) {
            int k0g = (ch + 1) * 32;
            #pragma unroll
            for (int u = 0; u < 2; u++) {
                int idx = t + u * 256, row = idx >> 3, c4 = (idx & 7) * 4;
                pf[u * 4 + 0] = *(const float4*)&g_hi[(jb + row) * ND + k0g + c4];
                pf[u * 4 + 1] = *(const float4*)&g_lo[(jb + row) * ND + k0g + c4];
                pf[u * 4 + 2] = *(const float4*)&g_hi[(kb + row) * ND + k0g + c4];
                pf[u * 4 + 3] = *(const float4*)&g_lo[(kb + row) * ND + k0g + c4];
            }
        }
        #pragma unroll
        for (int ks = 0; ks < 4; ks++) {
            int k0 = ks * 8;
            uint32_t ah0 = __float_as_uint(sAh[ar0 + k0]);
            uint32_t ah1 = __float_as_uint(sAh[ar0 + 8 * 36 + k0]);
            uint32_t ah2 = __float_as_uint(sAh[ar0 + k0 + 4]);
            uint32_t ah3 = __float_as_uint(sAh[ar0 + 8 * 36 + k0 + 4]);
            uint32_t al0 = __float_as_uint(sAl[ar0 + k0]);
            uint32_t al1 = __float_as_uint(sAl[ar0 + 8 * 36 + k0]);
            uint32_t al2 = __float_as_uint(sAl[ar0 + k0 + 4]);
            uint32_t al3 = __float_as_uint(sAl[ar0 + 8 * 36 + k0 + 4]);
            #pragma unroll
            for (int nb = 0; nb < 4; nb++) {
                int br = (wn + nb * 8 + (lane >> 2)) * 36 + k0 + (lane & 3);
                uint32_t bh0 = __float_as_uint(sBh[br]);
                uint32_t bh1 = __float_as_uint(sBh[br + 4]);
                uint32_t bl0 = __float_as_uint(sBl[br]);
                uint32_t bl1 = __float_as_uint(sBl[br + 4]);
                mma_tf32(acc[nb][0], acc[nb][1], acc[nb][2], acc[nb][3],
                         ah0, ah1, ah2, ah3, bh0, bh1);
                mma_tf32(acc[nb][0], acc[nb][1], acc[nb][2], acc[nb][3],
                         ah0, ah1, ah2, ah3, bl0, bl1);
                mma_tf32(acc[nb][0], acc[nb][1], acc[nb][2], acc[nb][3],
                         al0, al1, al2, al3, bh0, bh1);
            }
        }
    }

    // stage exp(result) in Tr[64][65] (aliases sbuf: 4160 <= 9216 floats)
    __syncthreads();
    float* Tr = sbuf;
    {
        int r0 = wr + (lane >> 2), c0 = wn + 2 * (lane & 3);
        #pragma unroll
        for (int nb = 0; nb < 4; nb++) {
            int cc = c0 + nb * 8;
            Tr[r0 * 65 + cc]           = __expf(acc[nb][0]);
            Tr[r0 * 65 + cc + 1]       = __expf(acc[nb][1]);
            Tr[(r0 + 8) * 65 + cc]     = __expf(acc[nb][2]);
            Tr[(r0 + 8) * 65 + cc + 1] = __expf(acc[nb][3]);
        }
    }
    __syncthreads();

    // coalesced E write
    #pragma unroll
    for (int u = 0; u < 4; u++) {
        int idx = t + u * 256;           // 1024 float4 = 64 rows x 16
        int r = idx >> 4, c4 = (idx & 15) * 4;
        float4 v = make_float4(Tr[r*65 + c4], Tr[r*65 + c4 + 1],
                               Tr[r*65 + c4 + 2], Tr[r*65 + c4 + 3]);
        *(float4*)&g_E[(jb + r) * NM + kb + c4] = v;
    }
    if (jt < 12) {
        if (jt != kt) {                  // transpose mirror
            #pragma unroll
            for (int u = 0; u < 4; u++) {
                int idx = t + u * 256;
                int r = idx >> 4, c4 = (idx & 15) * 4;
                float4 v = make_float4(Tr[(c4+0)*65 + r], Tr[(c4+1)*65 + r],
                                       Tr[(c4+2)*65 + r], Tr[(c4+3)*65 + r]);
                *(float4*)&g_E[(kb + r) * NM + jb + c4] = v;
            }
        }
    } else if (t < NB) {                 // anchor-row tile: csum (fixed-point)
        int mb = lab[t];
        float part = 0.f;
        #pragma unroll 8
        for (int cc = 0; cc < 64; cc++)
            if (lab[(kb + cc) >> 4] != mb) part += Tr[t * 65 + cc];
        atomicAdd(&g_csum[t], (unsigned long long)(long long)llrintf(part * SCALE_C));
    }
}

// ---- 2: warp-per-pair symmetric KL (cancellation-free) + in-kernel finish
// e=c*Et, a=c*Ea, t=e-a, mu=exp(e)-1 (series), d=mu-nu=t*h (series)
// h = 1 + u/2 + (u^2 - ea)/6 with u=e+a  (same series, fewer ops)
// symKL = 0.5*(Sdt*D1 - Sd*N1)/(D1*D2); D1=n+Smu, N1=St+Smut, D2=D1-Sd
// Pair order is irrelevant: per-pair kl is a pure function of globals and the
// accumulation is integer fixed-point -> bit-identical across replays.
__global__ void k_pairs(float* __restrict__ out) {
    __shared__ int lab[NB];
    __shared__ unsigned int ticket_s;
    int t = threadIdx.x, lane = t & 31, w = t >> 5;
    if (t < NB) lab[t] = g_lab[t];
    __syncthreads();
    int np = (int)g_pcnt;
    for (int p = blockIdx.x * 8 + w; p < np; p += PAIR_BLOCKS * 8) {
        int pr = g_pairs[p];
        int b = pr >> 16, j = pr & 0xffff;
        int mb = lab[b];
        float c = SCALE_C / (float)(long long)g_csum[b];
        const float* Et = g_E + j * NM;
        const float* Ea = g_E + (NM + b) * NM;

        float s0 = 0.f, s1 = 0.f, s2 = 0.f, s3 = 0.f, s4 = 0.f;
        #pragma unroll
        for (int i = 0; i < 6; i++) {    // float4 per lane; 4 k share one mask
            int k4 = i * 128 + lane * 4;
            float m = (lab[k4 >> 4] != mb) ? c : 0.f;
            float4 E4 = *(const float4*)&Et[k4];
            float4 A4 = *(const float4*)&Ea[k4];
            #pragma unroll
            for (int u4 = 0; u4 < 4; u4++) {
                float Ev = (u4 == 0) ? E4.x : (u4 == 1) ? E4.y : (u4 == 2) ? E4.z : E4.w;
                float Av = (u4 == 0) ? A4.x : (u4 == 1) ? A4.y : (u4 == 2) ? A4.z : A4.w;
                float e  = m * Ev;
                float a  = m * Av;
                float tt = e - a;
                float mu = e * fmaf(e, fmaf(e, 1.f/6.f, 0.5f), 1.f);
                float uu = e + a;
                float ea = e * a;
                float h  = fmaf(uu, fmaf(uu, 1.f/6.f, 0.5f), fmaf(ea, -1.f/6.f, 1.f));
                float d  = tt * h;
                s0 += tt; s1 += mu; s2 = fmaf(mu, tt, s2);
                s3 += d;  s4 = fmaf(tt, d, s4);
            }
        }
        #pragma unroll
        for (int o = 16; o > 0; o >>= 1) {
            s0 += __shfl_down_sync(0xffffffffu, s0, o);
            s1 += __shfl_down_sync(0xffffffffu, s1, o);
            s2 += __shfl_down_sync(0xffffffffu, s2, o);
            s3 += __shfl_down_sync(0xffffffffu, s3, o);
            s4 += __shfl_down_sync(0xffffffffu, s4, o);
        }
        if (lane == 0) {
            float n  = g_nneg[b];
            float D1 = n + s1;
            float N1 = s0 + s2;
            float D2 = D1 - s3;
            float kl = 0.5f * (s4 * D1 - s3 * N1) / (D1 * D2);
            atomicAdd(&g_rowsum[b],
                      (unsigned long long)(long long)llrintf(kl * SCALE_KL));
        }
    }
    // last block: final scalar + reset all counters for the next graph replay
    __threadfence();
    __syncthreads();
    if (t == 0) ticket_s = atomicAdd(&g_done, 1u);
    __syncthreads();
    if (ticket_s == PAIR_BLOCKS - 1 && t == 0) {
        float tot = 0.f;
        for (int b = 0; b < NB; b++) {
            float rs = (float)(long long)g_rowsum[b] * (1.f / SCALE_KL);
            tot += rs / g_P[b];
            g_rowsum[b] = 0ull;
            g_csum[b]   = 0ull;
        }
        out[0] = tot / (float)NB;
        g_pcnt = 0u;
        g_done = 0u;
    }
}

// ----------------------------------------------------------------- launch
extern "C" void kernel_launch(void* const* d_in, const int* in_sizes, int n_in,
                              void* d_out, int out_size) {
    const float* x     = (const float*)d_in[0];
    const int*   lab32 = (const int*)  d_in[1];
    float*       out   = (float*)      d_out;
    (void)in_sizes; (void)n_in; (void)out_size;

    k_prep <<<PREP_BLOCKS, 256>>>(x, lab32);
    k_gemm <<<NTILES, 256>>>();
    k_pairs<<<PAIR_BLOCKS, 256>>>(out);
}